// round 3
// baseline (speedup 1.0000x reference)
#include <cuda_runtime.h>
#include <cstdint>

// DynamicConv2d: B=64, C=8, H=W=256, OUT_C=8, K=3
// v2: single smem copy + 16B cp.async.cg; odd-aligned pairs rebuilt via
//     register packs; 4px x 2rows per thread; 16B output stores.

typedef unsigned long long ull;

#define NB   64
#define NC   8
#define NOC  8
#define HW   256

// 64 samples * 576 weights * 2 (duplicated pair halves)
__device__ float g_wp[NB * 1152];

// ---------------- Stage 1: weight generation ----------------
// pair index p = (ci*9 + ky*3 + kx)*8 + o
__global__ void gen_weights_kernel(const float* __restrict__ dw,
                                   const float* __restrict__ Wg,
                                   const float* __restrict__ bg) {
    int b = blockIdx.x;
    int p = threadIdx.x;
    if (p >= 576) return;
    int o = p & 7;
    int j = p >> 3;
    float s = bg[j];
    const float* dwp = dw + b * 64 + o * 8;
    const float* wgp = Wg + j * 8;
#pragma unroll
    for (int i = 0; i < 8; i++) s = fmaf(dwp[i], wgp[i], s);
    g_wp[b * 1152 + 2 * p]     = s;
    g_wp[b * 1152 + 2 * p + 1] = s;
}

// ---------------- Stage 2: convolution ----------------

__device__ __forceinline__ ull fma2(ull a, ull b, ull c) {
    ull d;
    asm("fma.rn.f32x2 %0, %1, %2, %3;" : "=l"(d) : "l"(a), "l"(b), "l"(c));
    return d;
}

__device__ __forceinline__ ull pack2(uint32_t lo, uint32_t hi) {
    ull d;
    asm("mov.b64 %0, {%1, %2};" : "=l"(d) : "r"(lo), "r"(hi));
    return d;
}

__device__ __forceinline__ void cp16(uint32_t saddr, const void* g, int srcsz) {
    asm volatile("cp.async.cg.shared.global [%0], [%1], %2, %3;\n"
                 :: "r"(saddr), "l"(g), "n"(16), "r"(srcsz));
}

#define SROWS 34            // 32 output rows + 2 halo
#define RST   76            // row stride in floats (72 data + 4 pad)
#define BUFSZ (SROWS * RST)
#define NCHUNK 18           // 16B chunks per row: global x in [x0-4, x0+68)

// block: 256 threads = 16 x-threads (4 px each -> 64 wide) x 16 y-threads (2 rows -> 32 tall)
// grid: (256/64, 256/32, 64)
__global__ void __launch_bounds__(256) conv_kernel(const float* __restrict__ x,
                                                   float* __restrict__ out) {
    __shared__ alignas(16) float sb[2 * BUFSZ + 1152];
    float* ws = sb + 2 * BUFSZ;

    const int b  = blockIdx.z;
    const int x0 = blockIdx.x * 64;
    const int y0 = blockIdx.y * 32;
    const int tid = threadIdx.x;
    const int xt = tid & 15;       // 4 px each
    const int ty = tid >> 4;       // 2 rows each

    // weights -> smem (float4 granularity)
    {
        const float4* src = (const float4*)(g_wp + b * 1152);
        float4* dst = (float4*)ws;
#pragma unroll
        for (int it = 0; it < 2; it++) {
            int i = tid + it * 256;
            if (i < 288) dst[i] = src[i];
        }
    }

    auto load_tile = [&](int bufi, int c) {
        float* dstf = sb + bufi * BUFSZ;
        uint32_t sbase = (uint32_t)__cvta_generic_to_shared(dstf);
        const float* xp = x + ((size_t)(b * NC + c)) * (HW * HW);
#pragma unroll
        for (int it = 0; it < 3; it++) {
            int i = tid + it * 256;
            if (i < SROWS * NCHUNK) {
                int row = i / NCHUNK;
                int k   = i - row * NCHUNK;
                int gy  = y0 - 1 + row;
                int gx0 = x0 - 4 + k * 4;
                // chunks are either fully in-bounds or fully out (x0 % 64 == 0)
                bool inb = ((unsigned)gy < (unsigned)HW) && ((unsigned)gx0 < (unsigned)HW);
                const float* src = inb ? (xp + gy * HW + gx0) : xp;
                cp16(sbase + (uint32_t)(row * RST + k * 4) * 4u, src, inb ? 16 : 0);
            }
        }
    };

    ull acc[2][2][8];
#pragma unroll
    for (int r = 0; r < 2; r++)
#pragma unroll
        for (int g = 0; g < 2; g++)
#pragma unroll
            for (int o = 0; o < 8; o++) acc[r][g][o] = 0ull;

    load_tile(0, 0);
    asm volatile("cp.async.commit_group;\n");
    asm volatile("cp.async.wait_group 0;\n");
    __syncthreads();

    for (int c = 0; c < NC; c++) {
        if (c < NC - 1) {
            load_tile((c + 1) & 1, c + 1);
            asm volatile("cp.async.commit_group;\n");
        }
        const float* cb = sb + (c & 1) * BUFSZ;
        const ull* wc = (const ull*)ws + c * 72;   // 72 pairs for channel c
#pragma unroll
        for (int ky = 0; ky < 3; ky++) {
            ull w2[24];                            // [kx*8 + o]
            {
                const ulonglong2* wv = (const ulonglong2*)(wc + ky * 24);
#pragma unroll
                for (int j = 0; j < 12; j++) {
                    ulonglong2 u = wv[j];
                    w2[2 * j]     = u.x;
                    w2[2 * j + 1] = u.y;
                }
            }
#pragma unroll
            for (int r = 0; r < 2; r++) {
                const float* rp = cb + (ty * 2 + r + ky) * RST;
                // px = x0 + 4*xt; smem idx of global g is g-(x0-4)
                const uint2* qp = (const uint2*)(rp + 4 * xt + 2);  // (px-2,px-1)
                uint2 q0 = qp[0];
                uint2 q1 = qp[1];   // (px,   px+1)
                uint2 q2 = qp[2];   // (px+2, px+3)
                uint2 q3 = qp[3];   // (px+4, px+5)
                ull A[5];
                A[0] = pack2(q0.y, q1.x);   // (px-1, px)
                A[1] = pack2(q1.x, q1.y);   // (px,   px+1)
                A[2] = pack2(q1.y, q2.x);   // (px+1, px+2)
                A[3] = pack2(q2.x, q2.y);   // (px+2, px+3)
                A[4] = pack2(q2.y, q3.x);   // (px+3, px+4)
#pragma unroll
                for (int kx = 0; kx < 3; kx++)
#pragma unroll
                    for (int g = 0; g < 2; g++) {
                        ull a = A[kx + 2 * g];
#pragma unroll
                        for (int o = 0; o < 8; o++)
                            acc[r][g][o] = fma2(a, w2[kx * 8 + o], acc[r][g][o]);
                    }
            }
        }
        if (c < NC - 1) asm volatile("cp.async.wait_group 0;\n");
        __syncthreads();
    }

    // epilogue: 16B stores (2 adjacent pairs = 4 pixels)
#pragma unroll
    for (int r = 0; r < 2; r++) {
        int gy = y0 + ty * 2 + r;
#pragma unroll
        for (int o = 0; o < 8; o++) {
            size_t idx = ((size_t)(b * NOC + o)) * (HW * HW) + (size_t)gy * HW + x0 + 4 * xt;
            ulonglong2 v;
            v.x = acc[r][0][o];
            v.y = acc[r][1][o];
            *(ulonglong2*)(out + idx) = v;
        }
    }
}

extern "C" void kernel_launch(void* const* d_in, const int* in_sizes, int n_in,
                              void* d_out, int out_size) {
    const float* x  = (const float*)d_in[0];
    const float* dw = (const float*)d_in[1];
    const float* Wg = (const float*)d_in[2];
    const float* bg = (const float*)d_in[3];
    float* out = (float*)d_out;

    gen_weights_kernel<<<NB, 576>>>(dw, Wg, bg);

    dim3 grid(HW / 64, HW / 32, NB);
    conv_kernel<<<grid, 256>>>(x, out);
}

// round 4
// speedup vs baseline: 2.0281x; 2.0281x over previous
#include <cuda_runtime.h>
#include <cstdint>

// DynamicConv2d: B=64, C=8, H=W=256, OUT_C=8, K=3
// v3: register-diet pack version.
//   - 1 row x 4 px per thread  -> acc[2][8] ull = 32 regs
//   - weights loaded per-kx    -> 16 live weight regs
//   - 16B cp.async.cg loader, 16B stores
//   - __launch_bounds__(256,3) -> target 3 CTAs/SM

typedef unsigned long long ull;

#define NB   64
#define NC   8
#define NOC  8
#define HW   256

// 64 samples * 576 weights * 2 (duplicated pair halves)
__device__ float g_wp[NB * 1152];

// ---------------- Stage 1: weight generation ----------------
// pair index p = (ci*9 + ky*3 + kx)*8 + o
__global__ void gen_weights_kernel(const float* __restrict__ dw,
                                   const float* __restrict__ Wg,
                                   const float* __restrict__ bg) {
    int b = blockIdx.x;
    int p = threadIdx.x;
    if (p >= 576) return;
    int o = p & 7;
    int j = p >> 3;
    float s = bg[j];
    const float* dwp = dw + b * 64 + o * 8;
    const float* wgp = Wg + j * 8;
#pragma unroll
    for (int i = 0; i < 8; i++) s = fmaf(dwp[i], wgp[i], s);
    g_wp[b * 1152 + 2 * p]     = s;
    g_wp[b * 1152 + 2 * p + 1] = s;
}

// ---------------- Stage 2: convolution ----------------

__device__ __forceinline__ ull fma2(ull a, ull b, ull c) {
    ull d;
    asm("fma.rn.f32x2 %0, %1, %2, %3;" : "=l"(d) : "l"(a), "l"(b), "l"(c));
    return d;
}

__device__ __forceinline__ ull pack2(uint32_t lo, uint32_t hi) {
    ull d;
    asm("mov.b64 %0, {%1, %2};" : "=l"(d) : "r"(lo), "r"(hi));
    return d;
}

__device__ __forceinline__ void cp16(uint32_t saddr, const void* g, int srcsz) {
    asm volatile("cp.async.cg.shared.global [%0], [%1], %2, %3;\n"
                 :: "r"(saddr), "l"(g), "n"(16), "r"(srcsz));
}

#define SROWS 18            // 16 output rows + 2 halo
#define RST   76            // row stride in floats (72 data + 4 pad), 16B-aligned
#define BUFSZ (SROWS * RST)
#define NCHUNK 18           // 16B chunks per row: global x in [x0-4, x0+68)

// block: 256 = 16 xt (4 px each -> 64 wide) x 16 ty (1 row each -> 16 tall)
// grid: (256/64, 256/16, 64) = (4, 16, 64)
__global__ void __launch_bounds__(256, 3) conv_kernel(const float* __restrict__ x,
                                                      float* __restrict__ out) {
    __shared__ alignas(16) float sb[2 * BUFSZ + 1152];
    float* ws = sb + 2 * BUFSZ;

    const int b  = blockIdx.z;
    const int x0 = blockIdx.x * 64;
    const int y0 = blockIdx.y * 16;
    const int tid = threadIdx.x;
    const int xt = tid & 15;       // 4 px each
    const int ty = tid >> 4;       // 1 row each

    // weights -> smem (float4 granularity): 288 float4
    {
        const float4* src = (const float4*)(g_wp + b * 1152);
        float4* dst = (float4*)ws;
#pragma unroll
        for (int it = 0; it < 2; it++) {
            int i = tid + it * 256;
            if (i < 288) dst[i] = src[i];
        }
    }

    auto load_tile = [&](int bufi, int c) {
        float* dstf = sb + bufi * BUFSZ;
        uint32_t sbase = (uint32_t)__cvta_generic_to_shared(dstf);
        const float* xp = x + ((size_t)(b * NC + c)) * (HW * HW);
#pragma unroll
        for (int it = 0; it < 2; it++) {
            int i = tid + it * 256;
            if (i < SROWS * NCHUNK) {
                int row = i / NCHUNK;
                int k   = i - row * NCHUNK;
                int gy  = y0 - 1 + row;
                int gx0 = x0 - 4 + k * 4;
                // chunks are fully in-bounds or fully out (x0 % 64 == 0)
                bool inb = ((unsigned)gy < (unsigned)HW) && ((unsigned)gx0 < (unsigned)HW);
                const float* src = inb ? (xp + gy * HW + gx0) : xp;
                cp16(sbase + (uint32_t)(row * RST + k * 4) * 4u, src, inb ? 16 : 0);
            }
        }
    };

    ull acc[2][8];
#pragma unroll
    for (int g = 0; g < 2; g++)
#pragma unroll
        for (int o = 0; o < 8; o++) acc[g][o] = 0ull;

    load_tile(0, 0);
    asm volatile("cp.async.commit_group;\n");
    asm volatile("cp.async.wait_group 0;\n");
    __syncthreads();

    for (int c = 0; c < NC; c++) {
        if (c < NC - 1) {
            load_tile((c + 1) & 1, c + 1);
            asm volatile("cp.async.commit_group;\n");
        }
        const float* cb = sb + (c & 1) * BUFSZ;
#pragma unroll
        for (int ky = 0; ky < 3; ky++) {
            // row pixels: px = x0 + 4*xt ; smem idx of global g is g-(x0-4)
            const float* rp = cb + (ty + ky) * RST;
            const uint2* qp = (const uint2*)(rp + 4 * xt + 2);  // (px-2,px-1)
            uint2 q0 = qp[0];
            uint2 q1 = qp[1];   // (px,   px+1)
            uint2 q2 = qp[2];   // (px+2, px+3)
            uint2 q3 = qp[3];   // (px+4, px+5)
            ull A[5];
            A[0] = pack2(q0.y, q1.x);            // (px-1, px)
            A[1] = pack2(q1.x, q1.y);            // (px,   px+1)
            A[2] = pack2(q1.y, q2.x);            // (px+1, px+2)
            A[3] = pack2(q2.x, q2.y);            // (px+2, px+3)
            A[4] = pack2(q2.y, q3.x);            // (px+3, px+4)
#pragma unroll
            for (int kx = 0; kx < 3; kx++) {
                // 8 broadcast weight pairs for (c,ky,kx): 4x LDS.128
                const ulonglong2* wv =
                    (const ulonglong2*)ws + ((c * 3 + ky) * 3 + kx) * 4;
                ull w0, w1, w2c, w3, w4, w5, w6, w7;
                { ulonglong2 u = wv[0]; w0 = u.x; w1 = u.y; }
                { ulonglong2 u = wv[1]; w2c = u.x; w3 = u.y; }
                { ulonglong2 u = wv[2]; w4 = u.x; w5 = u.y; }
                { ulonglong2 u = wv[3]; w6 = u.x; w7 = u.y; }
                ull a0 = A[kx];        // group 0: outs (px, px+1)
                ull a1 = A[kx + 2];    // group 1: outs (px+2, px+3)
                acc[0][0] = fma2(a0, w0, acc[0][0]);
                acc[0][1] = fma2(a0, w1, acc[0][1]);
                acc[0][2] = fma2(a0, w2c, acc[0][2]);
                acc[0][3] = fma2(a0, w3, acc[0][3]);
                acc[0][4] = fma2(a0, w4, acc[0][4]);
                acc[0][5] = fma2(a0, w5, acc[0][5]);
                acc[0][6] = fma2(a0, w6, acc[0][6]);
                acc[0][7] = fma2(a0, w7, acc[0][7]);
                acc[1][0] = fma2(a1, w0, acc[1][0]);
                acc[1][1] = fma2(a1, w1, acc[1][1]);
                acc[1][2] = fma2(a1, w2c, acc[1][2]);
                acc[1][3] = fma2(a1, w3, acc[1][3]);
                acc[1][4] = fma2(a1, w4, acc[1][4]);
                acc[1][5] = fma2(a1, w5, acc[1][5]);
                acc[1][6] = fma2(a1, w6, acc[1][6]);
                acc[1][7] = fma2(a1, w7, acc[1][7]);
            }
        }
        if (c < NC - 1) asm volatile("cp.async.wait_group 0;\n");
        __syncthreads();
    }

    // epilogue: 16B stores (4 adjacent pixels per (o))
    {
        int gy = y0 + ty;
#pragma unroll
        for (int o = 0; o < 8; o++) {
            size_t idx = ((size_t)(b * NOC + o)) * (HW * HW) + (size_t)gy * HW + x0 + 4 * xt;
            ulonglong2 v;
            v.x = acc[0][o];
            v.y = acc[1][o];
            *(ulonglong2*)(out + idx) = v;
        }
    }
}

extern "C" void kernel_launch(void* const* d_in, const int* in_sizes, int n_in,
                              void* d_out, int out_size) {
    const float* x  = (const float*)d_in[0];
    const float* dw = (const float*)d_in[1];
    const float* Wg = (const float*)d_in[2];
    const float* bg = (const float*)d_in[3];
    float* out = (float*)d_out;

    gen_weights_kernel<<<NB, 576>>>(dw, Wg, bg);

    dim3 grid(HW / 64, HW / 16, NB);
    conv_kernel<<<grid, 256>>>(x, out);
}

// round 7
// speedup vs baseline: 2.6482x; 1.3058x over previous
#include <cuda_runtime.h>
#include <cstdint>

// DynamicConv2d: B=64, C=8, H=W=256, OUT_C=8, K=3
// v4: o-pair f32x2 packing.
//   acc[g][op] = (out[2op], out[2op+1]) at pixel px+g  -> weight pairs are
//   natural adjacent floats (no duplication), pixel operand broadcast via
//   register dup-packs. Halves weight LDS traffic; 3 row LDS per ky.

typedef unsigned long long ull;

#define NB   64
#define NC   8
#define NOC  8
#define HW   256

// plain weights: 64 samples * 576 floats, p = (ci*9+ky*3+kx)*8 + o
__device__ float g_w[NB * 576];

// ---------------- Stage 1: weight generation ----------------
__global__ void gen_weights_kernel(const float* __restrict__ dw,
                                   const float* __restrict__ Wg,
                                   const float* __restrict__ bg) {
    int b = blockIdx.x;
    int p = threadIdx.x;
    if (p >= 576) return;
    int o = p & 7;
    int j = p >> 3;
    float s = bg[j];
    const float* dwp = dw + b * 64 + o * 8;
    const float* wgp = Wg + j * 8;
#pragma unroll
    for (int i = 0; i < 8; i++) s = fmaf(dwp[i], wgp[i], s);
    g_w[b * 576 + p] = s;
}

// ---------------- Stage 2: convolution ----------------

__device__ __forceinline__ ull fma2(ull a, ull b, ull c) {
    ull d;
    asm("fma.rn.f32x2 %0, %1, %2, %3;" : "=l"(d) : "l"(a), "l"(b), "l"(c));
    return d;
}

__device__ __forceinline__ ull pack2(uint32_t lo, uint32_t hi) {
    ull d;
    asm("mov.b64 %0, {%1, %2};" : "=l"(d) : "r"(lo), "r"(hi));
    return d;
}

__device__ __forceinline__ ull dup2(float v) {
    ull d;
    asm("mov.b64 %0, {%1, %1};" : "=l"(d) : "f"(v));
    return d;
}

__device__ __forceinline__ void cp16(uint32_t saddr, const void* g, int srcsz) {
    asm volatile("cp.async.cg.shared.global [%0], [%1], %2, %3;\n"
                 :: "r"(saddr), "l"(g), "n"(16), "r"(srcsz));
}

#define SROWS 18            // 16 output rows + 2 halo
#define RST   76            // row stride in floats (72 data + 4 pad), 16B-aligned
#define BUFSZ (SROWS * RST)
#define NCHUNK 18           // 16B chunks per row: global x in [x0-4, x0+68)

// block: 256 = 16 xt (4 px each -> 64 wide) x 16 ty (1 row each -> 16 tall)
// grid: (4, 16, 64)
__global__ void __launch_bounds__(256, 3) conv_kernel(const float* __restrict__ x,
                                                      float* __restrict__ out) {
    __shared__ alignas(16) float sb[2 * BUFSZ + 576];
    float* ws = sb + 2 * BUFSZ;

    const int b  = blockIdx.z;
    const int x0 = blockIdx.x * 64;
    const int y0 = blockIdx.y * 16;
    const int tid = threadIdx.x;
    const int xt = tid & 15;       // 4 px each
    const int ty = tid >> 4;       // 1 row each

    // weights -> smem: 144 float4
    {
        const float4* src = (const float4*)(g_w + b * 576);
        float4* dst = (float4*)ws;
        if (tid < 144) dst[tid] = src[tid];
    }

    auto load_tile = [&](int bufi, int c) {
        float* dstf = sb + bufi * BUFSZ;
        uint32_t sbase = (uint32_t)__cvta_generic_to_shared(dstf);
        const float* xp = x + ((size_t)(b * NC + c)) * (HW * HW);
#pragma unroll
        for (int it = 0; it < 2; it++) {
            int i = tid + it * 256;
            if (i < SROWS * NCHUNK) {
                int row = i / NCHUNK;
                int k   = i - row * NCHUNK;
                int gy  = y0 - 1 + row;
                int gx0 = x0 - 4 + k * 4;
                bool inb = ((unsigned)gy < (unsigned)HW) && ((unsigned)gx0 < (unsigned)HW);
                const float* src = inb ? (xp + gy * HW + gx0) : xp;
                cp16(sbase + (uint32_t)(row * RST + k * 4) * 4u, src, inb ? 16 : 0);
            }
        }
    };

    // acc[g][op] = f32x2 (out[2op], out[2op+1]) at pixel px0+g
    ull acc[4][4];
#pragma unroll
    for (int g = 0; g < 4; g++)
#pragma unroll
        for (int op = 0; op < 4; op++) acc[g][op] = 0ull;

    load_tile(0, 0);
    asm volatile("cp.async.commit_group;\n");
    asm volatile("cp.async.wait_group 0;\n");
    __syncthreads();

    for (int c = 0; c < NC; c++) {
        if (c < NC - 1) {
            load_tile((c + 1) & 1, c + 1);
            asm volatile("cp.async.commit_group;\n");
        }
        const float* cb = sb + (c & 1) * BUFSZ;
#pragma unroll
        for (int ky = 0; ky < 3; ky++) {
            // 12 natural weight pairs for (c,ky): [kx*4 + op] via 6 LDS.128
            ull w[12];
            {
                const ulonglong2* wv = (const ulonglong2*)ws + c * 18 + ky * 6;
#pragma unroll
                for (int j = 0; j < 6; j++) {
                    ulonglong2 u = wv[j];
                    w[2 * j]     = u.x;
                    w[2 * j + 1] = u.y;
                }
            }
            // row pixels px-1..px+4 (px = x0 + 4*xt; smem idx of g is g-(x0-4))
            const float* rp = cb + (ty + ky) * RST + 4 * xt;
            float4 m = *(const float4*)(rp + 4);   // px .. px+3
            float2 l = *(const float2*)(rp + 2);   // px-2, px-1
            float2 h = *(const float2*)(rp + 8);   // px+4, px+5
            ull P[6];
            P[0] = dup2(l.y);
            P[1] = dup2(m.x);
            P[2] = dup2(m.y);
            P[3] = dup2(m.z);
            P[4] = dup2(m.w);
            P[5] = dup2(h.x);
#pragma unroll
            for (int kx = 0; kx < 3; kx++) {
#pragma unroll
                for (int g = 0; g < 4; g++) {
                    ull a = P[g + kx];
                    acc[g][0] = fma2(a, w[kx * 4 + 0], acc[g][0]);
                    acc[g][1] = fma2(a, w[kx * 4 + 1], acc[g][1]);
                    acc[g][2] = fma2(a, w[kx * 4 + 2], acc[g][2]);
                    acc[g][3] = fma2(a, w[kx * 4 + 3], acc[g][3]);
                }
            }
        }
        if (c < NC - 1) asm volatile("cp.async.wait_group 0;\n");
        __syncthreads();
    }

    // epilogue: transpose o-pairs -> pixel-quad 16B stores
    {
        int gy = y0 + ty;
        size_t base = ((size_t)b * NOC) * (HW * HW) + (size_t)gy * HW + x0 + 4 * xt;
#pragma unroll
        for (int op = 0; op < 4; op++) {
            uint32_t lo[4], hi[4];
#pragma unroll
            for (int g = 0; g < 4; g++) {
                asm("mov.b64 {%0, %1}, %2;" : "=r"(lo[g]), "=r"(hi[g]) : "l"(acc[g][op]));
            }
            ulonglong2 v;
            v.x = pack2(lo[0], lo[1]);
            v.y = pack2(lo[2], lo[3]);
            *(ulonglong2*)(out + base + (size_t)(2 * op) * (HW * HW)) = v;
            v.x = pack2(hi[0], hi[1]);
            v.y = pack2(hi[2], hi[3]);
            *(ulonglong2*)(out + base + (size_t)(2 * op + 1) * (HW * HW)) = v;
        }
    }
}

extern "C" void kernel_launch(void* const* d_in, const int* in_sizes, int n_in,
                              void* d_out, int out_size) {
    const float* x  = (const float*)d_in[0];
    const float* dw = (const float*)d_in[1];
    const float* Wg = (const float*)d_in[2];
    const float* bg = (const float*)d_in[3];
    float* out = (float*)d_out;

    gen_weights_kernel<<<NB, 576>>>(dw, Wg, bg);

    dim3 grid(HW / 64, HW / 16, NB);
    conv_kernel<<<grid, 256>>>(x, out);
}